// round 15
// baseline (speedup 1.0000x reference)
#include <cuda_runtime.h>
#include <cstdint>

#define NSPB 32                    // sites per block
#define THREADS (NSPB * 9)         // 288
#define S_STRIDE 152               // floats per site (608B; conflict-free a/b residues)

__device__ __forceinline__ unsigned long long pack2(float lo, float hi) {
    unsigned long long r;
    asm("mov.b64 %0, {%1,%2};" : "=l"(r) : "f"(lo), "f"(hi));
    return r;
}
__device__ __forceinline__ void unpack2(unsigned long long v, float& lo, float& hi) {
    asm("mov.b64 {%0,%1}, %2;" : "=f"(lo), "=f"(hi) : "l"(v));
}
__device__ __forceinline__ unsigned long long ffma2(unsigned long long a, unsigned long long b,
                                                    unsigned long long c) {
    unsigned long long d;
    asm("fma.rn.f32x2 %0, %1, %2, %3;" : "=l"(d) : "l"(a), "l"(b), "l"(c));
    return d;
}
__device__ __forceinline__ unsigned long long fmul2(unsigned long long a, unsigned long long b) {
    unsigned long long d;
    asm("mul.rn.f32x2 %0, %1, %2;" : "=l"(d) : "l"(a), "l"(b));
    return d;
}

// acc{R,I}[0..3] += weight8(vw) * (cR,cR)/(cI,cI); weights via 2 broadcast LDS.128
__device__ __forceinline__ void mix_step(const ulonglong2* __restrict__ wt2, int vw,
                                         unsigned long long cpk,
                                         unsigned long long* accR,
                                         unsigned long long* accI)
{
    float cR, cI;
    unpack2(cpk, cR, cI);
    unsigned long long cRR = pack2(cR, cR);
    unsigned long long cII = pack2(cI, cI);
    ulonglong2 lo = wt2[vw * 2 + 0];    // (w0,w1),(w2,w3)
    ulonglong2 hi = wt2[vw * 2 + 1];    // (w4,w5),(w6,w7)
    accR[0] = ffma2(lo.x, cRR, accR[0]);
    accI[0] = ffma2(lo.x, cII, accI[0]);
    accR[1] = ffma2(lo.y, cRR, accR[1]);
    accI[1] = ffma2(lo.y, cII, accI[1]);
    accR[2] = ffma2(hi.x, cRR, accR[2]);
    accI[2] = ffma2(hi.x, cII, accI[2]);
    accR[3] = ffma2(hi.y, cRR, accR[3]);
    accI[3] = ffma2(hi.y, cII, accI[3]);
}

__global__ __launch_bounds__(THREADS, 4)
void lbilin_kernel(const float* __restrict__ u,
                   const float* __restrict__ w1,
                   const float* __restrict__ w2,
                   const float* __restrict__ weight,
                   float* __restrict__ out_u,
                   float* __restrict__ out_w)
{
    __shared__ __align__(16) float s_w1[NSPB * S_STRIDE];
    __shared__ __align__(16) float s_w2[NSPB * S_STRIDE];
    __shared__ __align__(16) float s_wt[81 * 8];   // s_wt[vw*8 + u] = weight[u*81 + vw]

    const int tid = threadIdx.x;
    const long long site0 = (long long)blockIdx.x * NSPB;

    // ---- u passthrough: 32 sites * 72 floats = 576 float4 per block ----
    {
        const float4* src = (const float4*)(u + site0 * 72);
        float4*       dst = (float4*)(out_u + site0 * 72);
        #pragma unroll
        for (int idx = tid; idx < NSPB * 18; idx += THREADS)
            dst[idx] = src[idx];
    }

    // ---- weight transpose into smem: [vw][u] (648 floats, L2-hot) ----
    for (int d = tid; d < 648; d += THREADS) {
        int uo = d & 7;
        int vw = d >> 3;
        s_wt[d] = weight[uo * 81 + vw];
    }

    // ---- stage w1, w2 tiles (144 contiguous floats/site), STS.128 ----
    {
        const float4* g1 = (const float4*)(w1 + site0 * 144);
        const float4* g2 = (const float4*)(w2 + site0 * 144);
        for (int idx = tid; idx < NSPB * 36; idx += THREADS) {
            int s = idx / 36;
            int q = idx - s * 36;
            ((float4*)(s_w1 + s * S_STRIDE))[q] = g1[idx];
            ((float4*)(s_w2 + s * S_STRIDE))[q] = g2[idx];
        }
    }
    __syncthreads();

    const int sl = tid / 9;
    const int ik = tid - sl * 9;
    const int i  = ik / 3;
    const int k  = ik - i * 3;

    const unsigned long long* w1p = (const unsigned long long*)(s_w1 + sl * S_STRIDE);
    const unsigned long long* w2p = (const unsigned long long*)(s_w2 + sl * S_STRIDE);
    const ulonglong2* wt2 = (const ulonglong2*)s_wt;

    // acc init = (v,w)=(8,8) contribution: c = (delta_ik, 0)
    unsigned long long accR[4], accI[4];
    {
        ulonglong2 lo = wt2[80 * 2 + 0];
        ulonglong2 hi = wt2[80 * 2 + 1];
        bool d = (i == k);
        accR[0] = d ? lo.x : 0ULL;
        accR[1] = d ? lo.y : 0ULL;
        accR[2] = d ? hi.x : 0ULL;
        accR[3] = d ? hi.y : 0ULL;
        #pragma unroll
        for (int h = 0; h < 4; h++) accI[h] = 0ULL;
    }

    const unsigned long long NEGPOS = pack2(-1.0f, 1.0f);

    // ---- four passes over w-pairs; b duplicated once per pass, a stays packed ----
    #pragma unroll 1
    for (int wbase = 0; wbase < 8; wbase += 2) {
        // load b packed, split into duplicated-real / duplicated-imag registers
        unsigned long long bR[6], bI[6];
        #pragma unroll
        for (int w = 0; w < 2; w++)
            #pragma unroll
            for (int j = 0; j < 3; j++) {
                unsigned long long bp = w2p[(wbase + w) * 9 + j * 3 + k];
                float br, bi;
                unpack2(bp, br, bi);
                bR[w * 3 + j] = pack2(br, br);
                bI[w * 3 + j] = pack2(bi, bi);
            }

        #pragma unroll 2
        for (int v = 0; v < 8; v++) {
            // a stays packed (aR, aI): direct LDS.64, no duplication movs
            unsigned long long a0 = w1p[v * 9 + i * 3 + 0];
            unsigned long long a1 = w1p[v * 9 + i * 3 + 1];
            unsigned long long a2 = w1p[v * 9 + i * 3 + 2];

            #pragma unroll
            for (int w = 0; w < 2; w++) {
                // P = (Sum aR*bR, Sum aI*bR) ; Q = (Sum aR*bI, Sum aI*bI)
                unsigned long long P = fmul2(a0, bR[w * 3 + 0]);
                P = ffma2(a1, bR[w * 3 + 1], P);
                P = ffma2(a2, bR[w * 3 + 2], P);
                unsigned long long Q = fmul2(a0, bI[w * 3 + 0]);
                Q = ffma2(a1, bI[w * 3 + 1], Q);
                Q = ffma2(a2, bI[w * 3 + 2], Q);
                // c = (P.lo - Q.hi, P.hi + Q.lo) = swap(Q)*(-1,+1) + P
                float ql, qh;
                unpack2(Q, ql, qh);
                unsigned long long cpk = ffma2(pack2(qh, ql), NEGPOS, P);
                mix_step(wt2, v * 9 + wbase + w, cpk, accR, accI);
            }
        }
        // v = 8: A is identity -> c[8,w] = B_w[i,k]
        #pragma unroll
        for (int w = 0; w < 2; w++)
            mix_step(wt2, 8 * 9 + wbase + w, w2p[(wbase + w) * 9 + i * 3 + k], accR, accI);
    }

    // w = 8 column: B identity -> c[v,8] = A_v[i,k]
    #pragma unroll
    for (int v = 0; v < 8; v++)
        mix_step(wt2, v * 9 + 8, w1p[v * 9 + i * 3 + k], accR, accI);

    // store w[u, i, k, {re,im}] : float2 at offset (u*9 + ik)*2
    float2* op = (float2*)(out_w + (site0 + sl) * 144 + ik * 2);
    #pragma unroll
    for (int h = 0; h < 4; h++) {
        float r0, r1, i0, i1;
        unpack2(accR[h], r0, r1);
        unpack2(accI[h], i0, i1);
        op[(2 * h + 0) * 9] = make_float2(r0, i0);
        op[(2 * h + 1) * 9] = make_float2(r1, i1);
    }
}

extern "C" void kernel_launch(void* const* d_in, const int* in_sizes, int n_in,
                              void* d_out, int out_size) {
    const float* u  = (const float*)d_in[0];
    const float* w1 = (const float*)d_in[1];
    const float* w2 = (const float*)d_in[2];
    const float* wt = (const float*)d_in[3];

    int nsites = in_sizes[1] / 144;          // 65536
    float* out   = (float*)d_out;
    float* out_u = out;                       // u passthrough first
    float* out_w = out + (long long)nsites * 72;  // then mixed output

    // single kernel: no prep nodes, weights transposed into smem per block
    int blocks = nsites / NSPB;               // 2048
    lbilin_kernel<<<blocks, THREADS>>>(u, w1, w2, wt, out_u, out_w);
}

// round 16
// speedup vs baseline: 1.0318x; 1.0318x over previous
#include <cuda_runtime.h>
#include <cstdint>

#define NSPB 32                    // sites per block
#define THREADS (NSPB * 9)         // 288
#define S_STRIDE 148               // floats per site in smem (144 + 4 pad)

__constant__ ulonglong2 c_wt2[162];    // [vw*2 + h]: ((w_u0,w_u1),(w_u2,w_u3)) | ((w_u4,w_u5),(w_u6,w_u7))

__device__ __forceinline__ unsigned long long pack2(float lo, float hi) {
    unsigned long long r;
    asm("mov.b64 %0, {%1,%2};" : "=l"(r) : "f"(lo), "f"(hi));
    return r;
}
__device__ __forceinline__ void unpack2(unsigned long long v, float& lo, float& hi) {
    asm("mov.b64 {%0,%1}, %2;" : "=f"(lo), "=f"(hi) : "l"(v));
}
__device__ __forceinline__ unsigned long long ffma2(unsigned long long a, unsigned long long b,
                                                    unsigned long long c) {
    unsigned long long d;
    asm("fma.rn.f32x2 %0, %1, %2, %3;" : "=l"(d) : "l"(a), "l"(b), "l"(c));
    return d;
}
__device__ __forceinline__ unsigned long long fmul2(unsigned long long a, unsigned long long b) {
    unsigned long long d;
    asm("mul.rn.f32x2 %0, %1, %2;" : "=l"(d) : "l"(a), "l"(b));
    return d;
}

// Transpose weight into [vw][u] layout, writing DIRECTLY into the constant
// bank's backing store (device address of c_wt2). Constant caches rebind at
// kernel-launch boundaries, so the subsequent main-kernel launch sees it.
__global__ void transpose_wt_kernel(const float* __restrict__ weight,
                                    float* __restrict__ cdst) {
    int d = threadIdx.x;
    if (d < 648) {
        int uo = d & 7;
        int vw = d >> 3;
        cdst[d] = weight[uo * 81 + vw];
    }
}

// acc{R,I}[0..3] += weight8(vw) * (cR,cR)/(cI,cI); weights from constant bank
__device__ __forceinline__ void mix_step(int vw, unsigned long long cpk,
                                         unsigned long long* accR,
                                         unsigned long long* accI)
{
    float cR, cI;
    unpack2(cpk, cR, cI);
    unsigned long long cRR = pack2(cR, cR);
    unsigned long long cII = pack2(cI, cI);
    ulonglong2 lo = c_wt2[vw * 2 + 0];    // (w0,w1),(w2,w3)
    ulonglong2 hi = c_wt2[vw * 2 + 1];    // (w4,w5),(w6,w7)
    accR[0] = ffma2(lo.x, cRR, accR[0]);
    accI[0] = ffma2(lo.x, cII, accI[0]);
    accR[1] = ffma2(lo.y, cRR, accR[1]);
    accI[1] = ffma2(lo.y, cII, accI[1]);
    accR[2] = ffma2(hi.x, cRR, accR[2]);
    accI[2] = ffma2(hi.x, cII, accI[2]);
    accR[3] = ffma2(hi.y, cRR, accR[3]);
    accI[3] = ffma2(hi.y, cII, accI[3]);
}

__global__ __launch_bounds__(THREADS, 4)
void lbilin_kernel(const float* __restrict__ u,
                   const float* __restrict__ w1,
                   const float* __restrict__ w2,
                   float* __restrict__ out_u,
                   float* __restrict__ out_w)
{
    __shared__ float s_w1[NSPB * S_STRIDE];
    __shared__ float s_w2[NSPB * S_STRIDE];

    const int tid = threadIdx.x;
    const long long site0 = (long long)blockIdx.x * NSPB;

    // ---- u passthrough: 32 sites * 72 floats = 576 float4 per block ----
    {
        const float4* src = (const float4*)(u + site0 * 72);
        float4*       dst = (float4*)(out_u + site0 * 72);
        #pragma unroll
        for (int idx = tid; idx < NSPB * 18; idx += THREADS)
            dst[idx] = src[idx];
    }

    // ---- stage w1, w2 tiles (144 contiguous floats/site) ----
    {
        const float4* g1 = (const float4*)(w1 + site0 * 144);
        const float4* g2 = (const float4*)(w2 + site0 * 144);
        for (int idx = tid; idx < NSPB * 36; idx += THREADS) {
            int s = idx / 36;
            int q = idx - s * 36;
            ((float4*)(s_w1 + s * S_STRIDE))[q] = g1[idx];
            ((float4*)(s_w2 + s * S_STRIDE))[q] = g2[idx];
        }
    }
    __syncthreads();

    const int sl = tid / 9;
    const int ik = tid - sl * 9;
    const int i  = ik / 3;
    const int k  = ik - i * 3;

    const unsigned long long* w1p = (const unsigned long long*)(s_w1 + sl * S_STRIDE);
    const unsigned long long* w2p = (const unsigned long long*)(s_w2 + sl * S_STRIDE);

    // acc init = (v,w)=(8,8) contribution: c = (delta_ik, 0)
    unsigned long long accR[4], accI[4];
    {
        ulonglong2 lo = c_wt2[80 * 2 + 0];
        ulonglong2 hi = c_wt2[80 * 2 + 1];
        bool d = (i == k);
        accR[0] = d ? lo.x : 0ULL;
        accR[1] = d ? lo.y : 0ULL;
        accR[2] = d ? hi.x : 0ULL;
        accR[3] = d ? hi.y : 0ULL;
        #pragma unroll
        for (int h = 0; h < 4; h++) accI[h] = 0ULL;
    }

    const unsigned long long NEGPOS = pack2(-1.0f, 1.0f);

    // ---- four passes over w-pairs; b duplicated once per pass, a stays packed ----
    #pragma unroll 1
    for (int wbase = 0; wbase < 8; wbase += 2) {
        // load b packed, split into duplicated-real / duplicated-imag registers
        unsigned long long bR[6], bI[6];
        #pragma unroll
        for (int w = 0; w < 2; w++)
            #pragma unroll
            for (int j = 0; j < 3; j++) {
                unsigned long long bp = w2p[(wbase + w) * 9 + j * 3 + k];
                float br, bi;
                unpack2(bp, br, bi);
                bR[w * 3 + j] = pack2(br, br);
                bI[w * 3 + j] = pack2(bi, bi);
            }

        #pragma unroll 2
        for (int v = 0; v < 8; v++) {
            // a stays packed (aR, aI): direct LDS.64, no duplication movs
            unsigned long long a0 = w1p[v * 9 + i * 3 + 0];
            unsigned long long a1 = w1p[v * 9 + i * 3 + 1];
            unsigned long long a2 = w1p[v * 9 + i * 3 + 2];

            #pragma unroll
            for (int w = 0; w < 2; w++) {
                // P = (Sum aR*bR, Sum aI*bR) ; Q = (Sum aR*bI, Sum aI*bI)
                unsigned long long P = fmul2(a0, bR[w * 3 + 0]);
                P = ffma2(a1, bR[w * 3 + 1], P);
                P = ffma2(a2, bR[w * 3 + 2], P);
                unsigned long long Q = fmul2(a0, bI[w * 3 + 0]);
                Q = ffma2(a1, bI[w * 3 + 1], Q);
                Q = ffma2(a2, bI[w * 3 + 2], Q);
                // c = (P.lo - Q.hi, P.hi + Q.lo) = swap(Q)*(-1,+1) + P
                float ql, qh;
                unpack2(Q, ql, qh);
                unsigned long long cpk = ffma2(pack2(qh, ql), NEGPOS, P);
                mix_step(v * 9 + wbase + w, cpk, accR, accI);
            }
        }
        // v = 8: A is identity -> c[8,w] = B_w[i,k]
        #pragma unroll
        for (int w = 0; w < 2; w++)
            mix_step(8 * 9 + wbase + w, w2p[(wbase + w) * 9 + i * 3 + k], accR, accI);
    }

    // w = 8 column: B identity -> c[v,8] = A_v[i,k]
    #pragma unroll
    for (int v = 0; v < 8; v++)
        mix_step(v * 9 + 8, w1p[v * 9 + i * 3 + k], accR, accI);

    // store w[u, i, k, {re,im}] : float2 at offset (u*9 + ik)*2
    float2* op = (float2*)(out_w + (site0 + sl) * 144 + ik * 2);
    #pragma unroll
    for (int h = 0; h < 4; h++) {
        float r0, r1, i0, i1;
        unpack2(accR[h], r0, r1);
        unpack2(accI[h], i0, i1);
        op[(2 * h + 0) * 9] = make_float2(r0, i0);
        op[(2 * h + 1) * 9] = make_float2(r1, i1);
    }
}

extern "C" void kernel_launch(void* const* d_in, const int* in_sizes, int n_in,
                              void* d_out, int out_size) {
    const float* u  = (const float*)d_in[0];
    const float* w1 = (const float*)d_in[1];
    const float* w2 = (const float*)d_in[2];
    const float* wt = (const float*)d_in[3];

    int nsites = in_sizes[1] / 144;          // 65536
    float* out   = (float*)d_out;
    float* out_u = out;                       // u passthrough first
    float* out_w = out + (long long)nsites * 72;  // then mixed output

    // 1) transpose weight, writing directly into the constant bank's backing
    //    store (no separate memcpy node needed)
    void* csym = nullptr;
    cudaGetSymbolAddress(&csym, c_wt2);
    transpose_wt_kernel<<<1, 648>>>(wt, (float*)csym);

    // 2) main kernel (constant cache rebinds at launch boundary)
    int blocks = nsites / NSPB;               // 2048
    lbilin_kernel<<<blocks, THREADS>>>(u, w1, w2, out_u, out_w);
}